// round 1
// baseline (speedup 1.0000x reference)
#include <cuda_runtime.h>
#include <math.h>

// ---------------------------------------------------------------------------
// DSDMSR: 4 stages of 4 SRCNN units (interleaved 2x upscale each) + MSF unit.
// SRCNN: conv 9x9 1->64 relu ; conv 5x5 64->32 relu ; conv 5x5 32->1.
// B=2, base 64x64. Outputs concatenated: x2(128^2), x4(256^2), x8(512^2),
// x16(1024^2), msf(1024^2), each B=2, C=1, float32.
// ---------------------------------------------------------------------------

#define NUM_UNITS 17

// Scratch (device globals: allocation-free, graph-capture safe).
// t1: up to 8 images x 64ch x 512^2 == 2 x 64 x 1024^2 (MSF) = 134217728 floats
__device__ float g_t1[134217728];       // 512 MB
__device__ float g_t2[67108864];        // 256 MB
__device__ float g_msf[2097152];        // 8 MB  (2 x 1024 x 1024)
// Transposed weights: w1t[unit][k(81)][co(64)], w2t[unit][ci(64)][k(25)][co(32)]
__device__ float g_w1t[NUM_UNITS * 81 * 64];
__device__ float g_w2t[NUM_UNITS * 64 * 25 * 32];

// ---------------------------------------------------------------------------
// Weight transpose prep (runs once per launch; tiny).
// w1: [17][64][1][9][9] -> g_w1t[u][k][co]
// w2: [17][32][64][5][5] -> g_w2t[u][ci][k][co]
// ---------------------------------------------------------------------------
__global__ void prep_weights(const float* __restrict__ w1,
                             const float* __restrict__ w2) {
    const int n1 = NUM_UNITS * 64 * 81;
    for (int i = blockIdx.x * blockDim.x + threadIdx.x; i < n1;
         i += gridDim.x * blockDim.x) {
        int unit = i / 5184;
        int r = i - unit * 5184;
        int co = r / 81;
        int k = r - co * 81;
        g_w1t[unit * 5184 + k * 64 + co] = w1[i];
    }
    const int n2 = NUM_UNITS * 32 * 64 * 25;
    for (int i = blockIdx.x * blockDim.x + threadIdx.x; i < n2;
         i += gridDim.x * blockDim.x) {
        int unit = i / 51200;
        int r = i - unit * 51200;
        int co = r / 1600;
        int r2 = r - co * 1600;
        int ci = r2 / 25;
        int k = r2 - ci * 25;
        g_w2t[((unit * 64 + ci) * 25 + k) * 32 + co] = w2[i];
    }
}

// ---------------------------------------------------------------------------
// conv1: 9x9, 1->64, bias, relu.  grid (W/16, H/16, B*numUnits), 256 threads.
// Each thread: 16 output channels x 4 consecutive x pixels.
// ---------------------------------------------------------------------------
__global__ __launch_bounds__(256) void conv1_kernel(
    const float* __restrict__ in, int fromMsf, const float* __restrict__ b1,
    int H, int W, int B, int unitBase) {
    __shared__ float s_in[24 * 24];
    __shared__ float s_w[81 * 64];
    __shared__ float s_b[64];

    int tid = threadIdx.x;
    int bz = blockIdx.z;
    int b = bz % B, uu = bz / B;
    int unit = unitBase + uu;

    const float* gin = (fromMsf ? g_msf : in) + (size_t)b * H * W;
    const float* gw = g_w1t + (size_t)unit * 5184;

    for (int i = tid; i < 5184; i += 256) s_w[i] = gw[i];
    if (tid < 64) s_b[tid] = b1[unit * 64 + tid];

    int bx0 = blockIdx.x * 16 - 4, by0 = blockIdx.y * 16 - 4;
    for (int i = tid; i < 576; i += 256) {
        int iy = i / 24, ix = i - iy * 24;
        int gy = by0 + iy, gx = bx0 + ix;
        float v = 0.f;
        if ((unsigned)gy < (unsigned)H && (unsigned)gx < (unsigned)W)
            v = gin[(size_t)gy * W + gx];
        s_in[i] = v;
    }
    __syncthreads();

    int cg = tid >> 6;                 // 0..3 -> co base cg*16
    int pg = tid & 63;
    int py = pg >> 2;                  // 0..15
    int x0 = (pg & 3) << 2;            // 0,4,8,12

    float acc[16][4];
#pragma unroll
    for (int j = 0; j < 16; j++)
#pragma unroll
        for (int p = 0; p < 4; p++) acc[j][p] = 0.f;

#pragma unroll 1
    for (int ky = 0; ky < 9; ky++) {
        const float* row = s_in + (py + ky) * 24 + x0;
        float4 a = *(const float4*)row;
        float4 c = *(const float4*)(row + 4);
        float4 d = *(const float4*)(row + 8);
        float in12[12] = {a.x, a.y, a.z, a.w, c.x, c.y,
                          c.z, c.w, d.x, d.y, d.z, d.w};
#pragma unroll
        for (int kx = 0; kx < 9; kx++) {
            const float* wb = s_w + (ky * 9 + kx) * 64 + cg * 16;
            float w[16];
#pragma unroll
            for (int j4 = 0; j4 < 4; j4++) {
                float4 t = *(const float4*)(wb + j4 * 4);
                w[j4 * 4 + 0] = t.x;
                w[j4 * 4 + 1] = t.y;
                w[j4 * 4 + 2] = t.z;
                w[j4 * 4 + 3] = t.w;
            }
#pragma unroll
            for (int j = 0; j < 16; j++)
#pragma unroll
                for (int p = 0; p < 4; p++) acc[j][p] += in12[kx + p] * w[j];
        }
    }

    size_t HW = (size_t)H * W;
    int y = blockIdx.y * 16 + py, x = blockIdx.x * 16 + x0;
    float* gout = g_t1 + (size_t)(uu * B + b) * 64 * HW;
#pragma unroll
    for (int j = 0; j < 16; j++) {
        int co = cg * 16 + j;
        float bias = s_b[co];
        float4 o;
        o.x = fmaxf(acc[j][0] + bias, 0.f);
        o.y = fmaxf(acc[j][1] + bias, 0.f);
        o.z = fmaxf(acc[j][2] + bias, 0.f);
        o.w = fmaxf(acc[j][3] + bias, 0.f);
        *(float4*)(gout + (size_t)co * HW + (size_t)y * W + x) = o;
    }
}

// ---------------------------------------------------------------------------
// conv2: 5x5, 64->32, bias, relu.  grid (W/16, H/16, B*numUnits), 256 threads.
// Each thread: 8 output channels x 4 consecutive x pixels.
// Input channels processed in chunks of 8 through shared memory.
// ---------------------------------------------------------------------------
__global__ __launch_bounds__(256) void conv2_kernel(
    const float* __restrict__ b2, int H, int W, int B, int unitBase) {
    __shared__ float s_in[8 * 400];     // [ci][20][20]
    __shared__ float s_w[8 * 25 * 32];  // [ci][k][co]

    int tid = threadIdx.x;
    int bz = blockIdx.z;
    int b = bz % B, uu = bz / B;
    int unit = unitBase + uu;

    int cg = tid >> 6;                  // 0..3 -> co base cg*8
    int pg = tid & 63;
    int py = pg >> 2;                   // 0..15
    int x0 = (pg & 3) << 2;             // 0,4,8,12
    int bx0 = blockIdx.x * 16 - 2, by0 = blockIdx.y * 16 - 2;

    size_t HW = (size_t)H * W;
    const float* gin = g_t1 + (size_t)(uu * B + b) * 64 * HW;
    const float* gw = g_w2t + (size_t)unit * 51200;

    float acc[8][4];
#pragma unroll
    for (int j = 0; j < 8; j++)
#pragma unroll
        for (int p = 0; p < 4; p++) acc[j][p] = 0.f;

    for (int cc = 0; cc < 8; cc++) {
        __syncthreads();
        for (int i = tid; i < 3200; i += 256) {
            int ci = i / 400;
            int r = i - ci * 400;
            int iy = r / 20, ix = r - iy * 20;
            int gy = by0 + iy, gx = bx0 + ix;
            float v = 0.f;
            if ((unsigned)gy < (unsigned)H && (unsigned)gx < (unsigned)W)
                v = gin[(size_t)(cc * 8 + ci) * HW + (size_t)gy * W + gx];
            s_in[i] = v;
        }
        for (int i = tid; i < 6400; i += 256) s_w[i] = gw[cc * 6400 + i];
        __syncthreads();

#pragma unroll 1
        for (int ci = 0; ci < 8; ci++) {
            const float* rowbase = s_in + ci * 400 + py * 20 + x0;
            const float* wci = s_w + ci * 25 * 32 + cg * 8;
#pragma unroll
            for (int ky = 0; ky < 5; ky++) {
                float4 ia = *(const float4*)(rowbase + ky * 20);
                float4 ib = *(const float4*)(rowbase + ky * 20 + 4);
                float in8[8] = {ia.x, ia.y, ia.z, ia.w,
                                ib.x, ib.y, ib.z, ib.w};
                const float* wb = wci + ky * 5 * 32;
#pragma unroll
                for (int kx = 0; kx < 5; kx++) {
                    float4 wlo = *(const float4*)(wb + kx * 32);
                    float4 whi = *(const float4*)(wb + kx * 32 + 4);
                    float w[8] = {wlo.x, wlo.y, wlo.z, wlo.w,
                                  whi.x, whi.y, whi.z, whi.w};
#pragma unroll
                    for (int p = 0; p < 4; p++) {
                        float iv = in8[kx + p];
#pragma unroll
                        for (int j = 0; j < 8; j++) acc[j][p] += iv * w[j];
                    }
                }
            }
        }
    }

    int y = blockIdx.y * 16 + py, x = blockIdx.x * 16 + x0;
    float* gout = g_t2 + (size_t)(uu * B + b) * 32 * HW;
#pragma unroll
    for (int j = 0; j < 8; j++) {
        int co = cg * 8 + j;
        float bias = b2[unit * 32 + co];
        float4 o;
        o.x = fmaxf(acc[j][0] + bias, 0.f);
        o.y = fmaxf(acc[j][1] + bias, 0.f);
        o.z = fmaxf(acc[j][2] + bias, 0.f);
        o.w = fmaxf(acc[j][3] + bias, 0.f);
        *(float4*)(gout + (size_t)co * HW + (size_t)y * W + x) = o;
    }
}

// ---------------------------------------------------------------------------
// conv3: 5x5, 32->1, bias.  Writes either interleaved (stage output, 2H x 2W)
// or plain (MSF output).  grid (W/16, H/16, B*numUnits), block (16,16).
// ---------------------------------------------------------------------------
__global__ __launch_bounds__(256) void conv3_kernel(
    const float* __restrict__ w3, const float* __restrict__ b3,
    float* __restrict__ out, int H, int W, int B, int unitBase,
    int interleave) {
    __shared__ float s_in[16 * 400];
    __shared__ float s_w[16 * 25];

    int tx = threadIdx.x, ty = threadIdx.y;
    int tid = ty * 16 + tx;
    int bz = blockIdx.z;
    int b = bz % B, uu = bz / B;
    int unit = unitBase + uu;

    size_t HW = (size_t)H * W;
    const float* gin = g_t2 + (size_t)(uu * B + b) * 32 * HW;
    const float* gw = w3 + (size_t)unit * 800;  // [ci(32)][5][5]
    int bx0 = blockIdx.x * 16 - 2, by0 = blockIdx.y * 16 - 2;

    float acc = 0.f;
    for (int cc = 0; cc < 2; cc++) {
        __syncthreads();
        for (int i = tid; i < 16 * 400; i += 256) {
            int ci = i / 400;
            int r = i - ci * 400;
            int iy = r / 20, ix = r - iy * 20;
            int gy = by0 + iy, gx = bx0 + ix;
            float v = 0.f;
            if ((unsigned)gy < (unsigned)H && (unsigned)gx < (unsigned)W)
                v = gin[(size_t)(cc * 16 + ci) * HW + (size_t)gy * W + gx];
            s_in[i] = v;
        }
        for (int i = tid; i < 400; i += 256) s_w[i] = gw[cc * 400 + i];
        __syncthreads();

#pragma unroll 1
        for (int ci = 0; ci < 16; ci++) {
#pragma unroll
            for (int ky = 0; ky < 5; ky++)
#pragma unroll
                for (int kx = 0; kx < 5; kx++)
                    acc += s_in[ci * 400 + (ty + ky) * 20 + tx + kx] *
                           s_w[ci * 25 + ky * 5 + kx];
        }
    }
    acc += b3[unit];

    int y = blockIdx.y * 16 + ty, x = blockIdx.x * 16 + tx;
    if (interleave) {
        int dy = uu >> 1, dx = uu & 1;
        out[(size_t)b * 4 * HW + (size_t)(2 * y + dy) * (2 * W) +
            (2 * x + dx)] = acc;
    } else {
        out[(size_t)b * HW + (size_t)y * W + x] = acc;
    }
}

// ---------------------------------------------------------------------------
// MSF input: bilinear upscales (jax.image.resize 'bilinear': half-pixel,
// edge-clamped) of x2/x4/x8 plus x16, into g_msf (2 x 1024 x 1024).
// ---------------------------------------------------------------------------
__device__ __forceinline__ float bilin(const float* __restrict__ p, int b,
                                       int H, int W, int oy, int ox, int s) {
    float sy = (oy + 0.5f) / (float)s - 0.5f;
    float sx = (ox + 0.5f) / (float)s - 0.5f;
    int y0 = (int)floorf(sy), x0 = (int)floorf(sx);
    float fy = sy - (float)y0, fx = sx - (float)x0;
    int y0c = min(max(y0, 0), H - 1), y1c = min(max(y0 + 1, 0), H - 1);
    int x0c = min(max(x0, 0), W - 1), x1c = min(max(x0 + 1, 0), W - 1);
    const float* pb = p + (size_t)b * H * W;
    float v00 = pb[(size_t)y0c * W + x0c];
    float v01 = pb[(size_t)y0c * W + x1c];
    float v10 = pb[(size_t)y1c * W + x0c];
    float v11 = pb[(size_t)y1c * W + x1c];
    return (1.f - fy) * ((1.f - fx) * v00 + fx * v01) +
           fy * ((1.f - fx) * v10 + fx * v11);
}

__global__ void msf_in_kernel(const float* __restrict__ x2,
                              const float* __restrict__ x4,
                              const float* __restrict__ x8,
                              const float* __restrict__ x16) {
    int idx = blockIdx.x * blockDim.x + threadIdx.x;
    if (idx >= 2 * 1024 * 1024) return;
    int b = idx >> 20;
    int r = idx & ((1 << 20) - 1);
    int y = r >> 10, x = r & 1023;
    float v = x16[idx];
    v += bilin(x2, b, 128, 128, y, x, 8);
    v += bilin(x4, b, 256, 256, y, x, 4);
    v += bilin(x8, b, 512, 512, y, x, 2);
    g_msf[idx] = v;
}

// ---------------------------------------------------------------------------
// Launch
// ---------------------------------------------------------------------------
extern "C" void kernel_launch(void* const* d_in, const int* in_sizes, int n_in,
                              void* d_out, int out_size) {
    const float* image = (const float*)d_in[0];
    const float* w1 = (const float*)d_in[1];
    const float* b1 = (const float*)d_in[2];
    const float* w2 = (const float*)d_in[3];
    const float* b2 = (const float*)d_in[4];
    const float* w3 = (const float*)d_in[5];
    const float* b3 = (const float*)d_in[6];
    float* out = (float*)d_out;

    float* o_x2 = out;                // 2*128*128  = 32768
    float* o_x4 = out + 32768;        // 2*256*256  = 131072
    float* o_x8 = out + 163840;       // 2*512*512  = 524288
    float* o_x16 = out + 688128;      // 2*1024*1024 = 2097152
    float* o_msf = out + 2785280;     // 2*1024*1024 = 2097152
    const int B = 2;

    prep_weights<<<256, 256>>>(w1, w2);

    // ---- stage helper (inline) ----
    // stage 1: in=image H=64  -> o_x2
    // stage 2: in=o_x2 H=128  -> o_x4
    // stage 3: in=o_x4 H=256  -> o_x8
    // stage 4: in=o_x8 H=512  -> o_x16
    const float* sin[4] = {image, o_x2, o_x4, o_x8};
    float* sout[4] = {o_x2, o_x4, o_x8, o_x16};
    int sH[4] = {64, 128, 256, 512};
    for (int s = 0; s < 4; s++) {
        int H = sH[s], W = sH[s];
        int ub = s * 4;
        dim3 grid(W / 16, H / 16, B * 4);
        conv1_kernel<<<grid, 256>>>(sin[s], 0, b1, H, W, B, ub);
        conv2_kernel<<<grid, 256>>>(b2, H, W, B, ub);
        conv3_kernel<<<grid, dim3(16, 16)>>>(w3, b3, sout[s], H, W, B, ub, 1);
    }

    // MSF input and final unit (unit 16) at 1024x1024
    msf_in_kernel<<<(2 * 1024 * 1024) / 256, 256>>>(o_x2, o_x4, o_x8, o_x16);
    {
        int H = 1024, W = 1024;
        dim3 grid(W / 16, H / 16, B * 1);
        conv1_kernel<<<grid, 256>>>(nullptr, 1, b1, H, W, B, 16);
        conv2_kernel<<<grid, 256>>>(b2, H, W, B, 16);
        conv3_kernel<<<grid, dim3(16, 16)>>>(w3, b3, o_msf, H, W, B, 16, 0);
    }
}

// round 4
// speedup vs baseline: 1.1125x; 1.1125x over previous
#include <cuda_runtime.h>
#include <math.h>

// ---------------------------------------------------------------------------
// DSDMSR: 4 stages of 4 SRCNN units (interleaved 2x upscale each) + MSF unit.
// SRCNN: conv 9x9 1->64 relu ; conv 5x5 64->32 relu ; conv 5x5 32->1.
// Round 4 (= Round 2 kernel, resubmitted verbatim; broker timeouts in R2/R3):
// packed fp32 math (fma.rn.f32x2 / FFMA2) in conv1+conv2 mainloops.
// FFMA-3reg is half-rate on sm_103a (rt_SMSP=2); FFMA2 doubles fp32
// throughput and is only reachable via explicit PTX.
// ---------------------------------------------------------------------------

#define NUM_UNITS 17

typedef unsigned long long u64;

__device__ __forceinline__ u64 pack_dup(float v) {
    u64 r;
    asm("mov.b64 %0, {%1, %2};" : "=l"(r) : "f"(v), "f"(v));
    return r;
}
__device__ __forceinline__ void ffma2(u64& d, u64 a, u64 b) {
    asm("fma.rn.f32x2 %0, %1, %2, %0;" : "+l"(d) : "l"(a), "l"(b));
}
__device__ __forceinline__ float2 unpack2(u64 v) {
    float2 f;
    asm("mov.b64 {%0, %1}, %2;" : "=f"(f.x), "=f"(f.y) : "l"(v));
    return f;
}

// Scratch (device globals: allocation-free, graph-capture safe).
__device__ float g_t1[134217728];       // 512 MB  (conv1 outputs, 64ch)
__device__ float g_t2[67108864];        // 256 MB  (conv2 outputs, 32ch)
__device__ float g_msf[2097152];        // 8 MB    (2 x 1024 x 1024)
// Transposed weights: w1t[unit][k(81)][co(64)], w2t[unit][ci(64)][k(25)][co(32)]
__device__ float g_w1t[NUM_UNITS * 81 * 64];
__device__ float g_w2t[NUM_UNITS * 64 * 25 * 32];

// ---------------------------------------------------------------------------
// Weight transpose prep (tiny, once per launch).
// ---------------------------------------------------------------------------
__global__ void prep_weights(const float* __restrict__ w1,
                             const float* __restrict__ w2) {
    const int n1 = NUM_UNITS * 64 * 81;
    for (int i = blockIdx.x * blockDim.x + threadIdx.x; i < n1;
         i += gridDim.x * blockDim.x) {
        int unit = i / 5184;
        int r = i - unit * 5184;
        int co = r / 81;
        int k = r - co * 81;
        g_w1t[unit * 5184 + k * 64 + co] = w1[i];
    }
    const int n2 = NUM_UNITS * 32 * 64 * 25;
    for (int i = blockIdx.x * blockDim.x + threadIdx.x; i < n2;
         i += gridDim.x * blockDim.x) {
        int unit = i / 51200;
        int r = i - unit * 51200;
        int co = r / 1600;
        int r2 = r - co * 1600;
        int ci = r2 / 25;
        int k = r2 - ci * 25;
        g_w2t[((unit * 64 + ci) * 25 + k) * 32 + co] = w2[i];
    }
}

// ---------------------------------------------------------------------------
// conv1: 9x9, 1->64, bias, relu. grid (W/16, H/16, B*numUnits), 256 threads.
// Each thread: 16 output channels (8 packed pairs) x 4 consecutive x pixels.
// ---------------------------------------------------------------------------
__global__ __launch_bounds__(256) void conv1_kernel(
    const float* __restrict__ in, int fromMsf, const float* __restrict__ b1,
    int H, int W, int B, int unitBase) {
    __shared__ float s_in[24 * 24];
    __shared__ float s_w[81 * 64];
    __shared__ float s_b[64];

    int tid = threadIdx.x;
    int bz = blockIdx.z;
    int b = bz % B, uu = bz / B;
    int unit = unitBase + uu;

    const float* gin = (fromMsf ? g_msf : in) + (size_t)b * H * W;
    const float* gw = g_w1t + (size_t)unit * 5184;

    for (int i = tid; i < 5184; i += 256) s_w[i] = gw[i];
    if (tid < 64) s_b[tid] = b1[unit * 64 + tid];

    int bx0 = blockIdx.x * 16 - 4, by0 = blockIdx.y * 16 - 4;
    for (int i = tid; i < 576; i += 256) {
        int iy = i / 24, ix = i - iy * 24;
        int gy = by0 + iy, gx = bx0 + ix;
        float v = 0.f;
        if ((unsigned)gy < (unsigned)H && (unsigned)gx < (unsigned)W)
            v = gin[(size_t)gy * W + gx];
        s_in[i] = v;
    }
    __syncthreads();

    int cg = tid >> 6;                 // 0..3 -> co base cg*16
    int pg = tid & 63;
    int py = pg >> 2;                  // 0..15
    int x0 = (pg & 3) << 2;            // 0,4,8,12

    // acc2[jp][p]: jp = channel pair (co = cg*16 + 2jp, +1), p = pixel 0..3
    u64 acc2[8][4];
#pragma unroll
    for (int j = 0; j < 8; j++)
#pragma unroll
        for (int p = 0; p < 4; p++) acc2[j][p] = 0ull;

#pragma unroll 1
    for (int ky = 0; ky < 9; ky++) {
        const float* row = s_in + (py + ky) * 24 + x0;
        float4 a = *(const float4*)row;
        float4 c = *(const float4*)(row + 4);
        float4 d = *(const float4*)(row + 8);
        float in12[12] = {a.x, a.y, a.z, a.w, c.x, c.y,
                          c.z, c.w, d.x, d.y, d.z, d.w};
        u64 dup[12];
#pragma unroll
        for (int i = 0; i < 12; i++) dup[i] = pack_dup(in12[i]);
#pragma unroll
        for (int kx = 0; kx < 9; kx++) {
            const float* wb = s_w + (ky * 9 + kx) * 64 + cg * 16;
            ulonglong2 wA = *(const ulonglong2*)(wb);       // pairs 0,1
            ulonglong2 wB = *(const ulonglong2*)(wb + 4);   // pairs 2,3
            ulonglong2 wC = *(const ulonglong2*)(wb + 8);   // pairs 4,5
            ulonglong2 wD = *(const ulonglong2*)(wb + 12);  // pairs 6,7
            u64 wp[8] = {wA.x, wA.y, wB.x, wB.y, wC.x, wC.y, wD.x, wD.y};
#pragma unroll
            for (int p = 0; p < 4; p++) {
                u64 iv = dup[kx + p];
#pragma unroll
                for (int j = 0; j < 8; j++) ffma2(acc2[j][p], wp[j], iv);
            }
        }
    }

    size_t HW = (size_t)H * W;
    int y = blockIdx.y * 16 + py, x = blockIdx.x * 16 + x0;
    float* gout = g_t1 + (size_t)(uu * B + b) * 64 * HW;
#pragma unroll
    for (int j = 0; j < 8; j++) {
        int co0 = cg * 16 + 2 * j;
        float b0 = s_b[co0], b1v = s_b[co0 + 1];
        float2 v0 = unpack2(acc2[j][0]);
        float2 v1 = unpack2(acc2[j][1]);
        float2 v2 = unpack2(acc2[j][2]);
        float2 v3 = unpack2(acc2[j][3]);
        float4 oA = {fmaxf(v0.x + b0, 0.f), fmaxf(v1.x + b0, 0.f),
                     fmaxf(v2.x + b0, 0.f), fmaxf(v3.x + b0, 0.f)};
        float4 oB = {fmaxf(v0.y + b1v, 0.f), fmaxf(v1.y + b1v, 0.f),
                     fmaxf(v2.y + b1v, 0.f), fmaxf(v3.y + b1v, 0.f)};
        *(float4*)(gout + (size_t)co0 * HW + (size_t)y * W + x) = oA;
        *(float4*)(gout + (size_t)(co0 + 1) * HW + (size_t)y * W + x) = oB;
    }
}

// ---------------------------------------------------------------------------
// conv2: 5x5, 64->32, bias, relu. grid (W/16, H/16, B*numUnits), 256 threads.
// Each thread: 8 output channels (4 packed pairs) x 4 consecutive x pixels.
// Input channels processed in chunks of 8 through shared memory.
// ---------------------------------------------------------------------------
__global__ __launch_bounds__(256) void conv2_kernel(
    const float* __restrict__ b2, int H, int W, int B, int unitBase) {
    __shared__ float s_in[8 * 400];     // [ci][20][20]
    __shared__ float s_w[8 * 25 * 32];  // [ci][k][co]

    int tid = threadIdx.x;
    int bz = blockIdx.z;
    int b = bz % B, uu = bz / B;
    int unit = unitBase + uu;

    int cg = tid >> 6;                  // 0..3 -> co base cg*8
    int pg = tid & 63;
    int py = pg >> 2;                   // 0..15
    int x0 = (pg & 3) << 2;             // 0,4,8,12
    int bx0 = blockIdx.x * 16 - 2, by0 = blockIdx.y * 16 - 2;

    size_t HW = (size_t)H * W;
    const float* gin = g_t1 + (size_t)(uu * B + b) * 64 * HW;
    const float* gw = g_w2t + (size_t)unit * 51200;

    // acc2[jp][p]: jp = channel pair (co = cg*8 + 2jp, +1), p = pixel 0..3
    u64 acc2[4][4];
#pragma unroll
    for (int j = 0; j < 4; j++)
#pragma unroll
        for (int p = 0; p < 4; p++) acc2[j][p] = 0ull;

    for (int cc = 0; cc < 8; cc++) {
        __syncthreads();
        for (int i = tid; i < 3200; i += 256) {
            int ci = i / 400;
            int r = i - ci * 400;
            int iy = r / 20, ix = r - iy * 20;
            int gy = by0 + iy, gx = bx0 + ix;
            float v = 0.f;
            if ((unsigned)gy < (unsigned)H && (unsigned)gx < (unsigned)W)
                v = gin[(size_t)(cc * 8 + ci) * HW + (size_t)gy * W + gx];
            s_in[i] = v;
        }
        for (int i = tid; i < 6400; i += 256) s_w[i] = gw[cc * 6400 + i];
        __syncthreads();

#pragma unroll 1
        for (int ci = 0; ci < 8; ci++) {
            const float* rowbase = s_in + ci * 400 + py * 20 + x0;
            const float* wci = s_w + ci * 25 * 32 + cg * 8;
#pragma unroll
            for (int ky = 0; ky < 5; ky++) {
                float4 ia = *(const float4*)(rowbase + ky * 20);
                float4 ib = *(const float4*)(rowbase + ky * 20 + 4);
                float in8[8] = {ia.x, ia.y, ia.z, ia.w,
                                ib.x, ib.y, ib.z, ib.w};
                u64 dup[8];
#pragma unroll
                for (int i = 0; i < 8; i++) dup[i] = pack_dup(in8[i]);
                const float* wb = wci + ky * 5 * 32;
#pragma unroll
                for (int kx = 0; kx < 5; kx++) {
                    ulonglong2 wl = *(const ulonglong2*)(wb + kx * 32);
                    ulonglong2 wh = *(const ulonglong2*)(wb + kx * 32 + 4);
                    u64 wp[4] = {wl.x, wl.y, wh.x, wh.y};
#pragma unroll
                    for (int p = 0; p < 4; p++) {
                        u64 iv = dup[kx + p];
#pragma unroll
                        for (int j = 0; j < 4; j++) ffma2(acc2[j][p], wp[j], iv);
                    }
                }
            }
        }
    }

    int y = blockIdx.y * 16 + py, x = blockIdx.x * 16 + x0;
    float* gout = g_t2 + (size_t)(uu * B + b) * 32 * HW;
#pragma unroll
    for (int j = 0; j < 4; j++) {
        int co0 = cg * 8 + 2 * j;
        float b0 = b2[unit * 32 + co0], b1v = b2[unit * 32 + co0 + 1];
        float2 v0 = unpack2(acc2[j][0]);
        float2 v1 = unpack2(acc2[j][1]);
        float2 v2 = unpack2(acc2[j][2]);
        float2 v3 = unpack2(acc2[j][3]);
        float4 oA = {fmaxf(v0.x + b0, 0.f), fmaxf(v1.x + b0, 0.f),
                     fmaxf(v2.x + b0, 0.f), fmaxf(v3.x + b0, 0.f)};
        float4 oB = {fmaxf(v0.y + b1v, 0.f), fmaxf(v1.y + b1v, 0.f),
                     fmaxf(v2.y + b1v, 0.f), fmaxf(v3.y + b1v, 0.f)};
        *(float4*)(gout + (size_t)co0 * HW + (size_t)y * W + x) = oA;
        *(float4*)(gout + (size_t)(co0 + 1) * HW + (size_t)y * W + x) = oB;
    }
}

// ---------------------------------------------------------------------------
// conv3: 5x5, 32->1, bias. Writes interleaved (stage) or plain (MSF).
// ---------------------------------------------------------------------------
__global__ __launch_bounds__(256) void conv3_kernel(
    const float* __restrict__ w3, const float* __restrict__ b3,
    float* __restrict__ out, int H, int W, int B, int unitBase,
    int interleave) {
    __shared__ float s_in[16 * 400];
    __shared__ float s_w[16 * 25];

    int tx = threadIdx.x, ty = threadIdx.y;
    int tid = ty * 16 + tx;
    int bz = blockIdx.z;
    int b = bz % B, uu = bz / B;
    int unit = unitBase + uu;

    size_t HW = (size_t)H * W;
    const float* gin = g_t2 + (size_t)(uu * B + b) * 32 * HW;
    const float* gw = w3 + (size_t)unit * 800;  // [ci(32)][5][5]
    int bx0 = blockIdx.x * 16 - 2, by0 = blockIdx.y * 16 - 2;

    float acc = 0.f;
    for (int cc = 0; cc < 2; cc++) {
        __syncthreads();
        for (int i = tid; i < 16 * 400; i += 256) {
            int ci = i / 400;
            int r = i - ci * 400;
            int iy = r / 20, ix = r - iy * 20;
            int gy = by0 + iy, gx = bx0 + ix;
            float v = 0.f;
            if ((unsigned)gy < (unsigned)H && (unsigned)gx < (unsigned)W)
                v = gin[(size_t)(cc * 16 + ci) * HW + (size_t)gy * W + gx];
            s_in[i] = v;
        }
        for (int i = tid; i < 400; i += 256) s_w[i] = gw[cc * 400 + i];
        __syncthreads();

#pragma unroll 1
        for (int ci = 0; ci < 16; ci++) {
#pragma unroll
            for (int ky = 0; ky < 5; ky++)
#pragma unroll
                for (int kx = 0; kx < 5; kx++)
                    acc += s_in[ci * 400 + (ty + ky) * 20 + tx + kx] *
                           s_w[ci * 25 + ky * 5 + kx];
        }
    }
    acc += b3[unit];

    int y = blockIdx.y * 16 + ty, x = blockIdx.x * 16 + tx;
    if (interleave) {
        int dy = uu >> 1, dx = uu & 1;
        out[(size_t)b * 4 * HW + (size_t)(2 * y + dy) * (2 * W) +
            (2 * x + dx)] = acc;
    } else {
        out[(size_t)b * HW + (size_t)y * W + x] = acc;
    }
}

// ---------------------------------------------------------------------------
// MSF input: bilinear upscales (half-pixel, edge-clamped) + x16.
// ---------------------------------------------------------------------------
__device__ __forceinline__ float bilin(const float* __restrict__ p, int b,
                                       int H, int W, int oy, int ox, int s) {
    float sy = (oy + 0.5f) / (float)s - 0.5f;
    float sx = (ox + 0.5f) / (float)s - 0.5f;
    int y0 = (int)floorf(sy), x0 = (int)floorf(sx);
    float fy = sy - (float)y0, fx = sx - (float)x0;
    int y0c = min(max(y0, 0), H - 1), y1c = min(max(y0 + 1, 0), H - 1);
    int x0c = min(max(x0, 0), W - 1), x1c = min(max(x0 + 1, 0), W - 1);
    const float* pb = p + (size_t)b * H * W;
    float v00 = pb[(size_t)y0c * W + x0c];
    float v01 = pb[(size_t)y0c * W + x1c];
    float v10 = pb[(size_t)y1c * W + x0c];
    float v11 = pb[(size_t)y1c * W + x1c];
    return (1.f - fy) * ((1.f - fx) * v00 + fx * v01) +
           fy * ((1.f - fx) * v10 + fx * v11);
}

__global__ void msf_in_kernel(const float* __restrict__ x2,
                              const float* __restrict__ x4,
                              const float* __restrict__ x8,
                              const float* __restrict__ x16) {
    int idx = blockIdx.x * blockDim.x + threadIdx.x;
    if (idx >= 2 * 1024 * 1024) return;
    int b = idx >> 20;
    int r = idx & ((1 << 20) - 1);
    int y = r >> 10, x = r & 1023;
    float v = x16[idx];
    v += bilin(x2, b, 128, 128, y, x, 8);
    v += bilin(x4, b, 256, 256, y, x, 4);
    v += bilin(x8, b, 512, 512, y, x, 2);
    g_msf[idx] = v;
}

// ---------------------------------------------------------------------------
// Launch
// ---------------------------------------------------------------------------
extern "C" void kernel_launch(void* const* d_in, const int* in_sizes, int n_in,
                              void* d_out, int out_size) {
    const float* image = (const float*)d_in[0];
    const float* w1 = (const float*)d_in[1];
    const float* b1 = (const float*)d_in[2];
    const float* w2 = (const float*)d_in[3];
    const float* b2 = (const float*)d_in[4];
    const float* w3 = (const float*)d_in[5];
    const float* b3 = (const float*)d_in[6];
    float* out = (float*)d_out;

    float* o_x2 = out;                // 2*128*128  = 32768
    float* o_x4 = out + 32768;        // 2*256*256  = 131072
    float* o_x8 = out + 163840;       // 2*512*512  = 524288
    float* o_x16 = out + 688128;      // 2*1024*1024 = 2097152
    float* o_msf = out + 2785280;     // 2*1024*1024 = 2097152
    const int B = 2;

    prep_weights<<<256, 256>>>(w1, w2);

    const float* sin[4] = {image, o_x2, o_x4, o_x8};
    float* sout[4] = {o_x2, o_x4, o_x8, o_x16};
    int sH[4] = {64, 128, 256, 512};
    for (int s = 0; s < 4; s++) {
        int H = sH[s], W = sH[s];
        int ub = s * 4;
        dim3 grid(W / 16, H / 16, B * 4);
        conv1_kernel<<<grid, 256>>>(sin[s], 0, b1, H, W, B, ub);
        conv2_kernel<<<grid, 256>>>(b2, H, W, B, ub);
        conv3_kernel<<<grid, dim3(16, 16)>>>(w3, b3, sout[s], H, W, B, ub, 1);
    }

    msf_in_kernel<<<(2 * 1024 * 1024) / 256, 256>>>(o_x2, o_x4, o_x8, o_x16);
    {
        int H = 1024, W = 1024;
        dim3 grid(W / 16, H / 16, B * 1);
        conv1_kernel<<<grid, 256>>>(nullptr, 1, b1, H, W, B, 16);
        conv2_kernel<<<grid, 256>>>(b2, H, W, B, 16);
        conv3_kernel<<<grid, dim3(16, 16)>>>(w3, b3, o_msf, H, W, B, 16, 0);
    }
}

// round 7
// speedup vs baseline: 1.1735x; 1.0549x over previous
#include <cuda_runtime.h>
#include <stdint.h>
#include <math.h>

// ---------------------------------------------------------------------------
// DSDMSR: 4 stages of 4 SRCNN units (interleaved 2x upscale each) + MSF unit.
// SRCNN: conv 9x9 1->64 relu ; conv 5x5 64->32 relu ; conv 5x5 32->1.
// Round 7 (= Round 5 kernel + missing <stdint.h>; R6 failed to compile):
// FFMA2 (fma.rn.f32x2) mainloops + double-buffered cp.async pipeline in
// conv2 (the 90% term) to overlap smem fills with compute.
// ---------------------------------------------------------------------------

#define NUM_UNITS 17

typedef unsigned long long u64;

__device__ __forceinline__ u64 pack_dup(float v) {
    u64 r;
    asm("mov.b64 %0, {%1, %2};" : "=l"(r) : "f"(v), "f"(v));
    return r;
}
__device__ __forceinline__ void ffma2(u64& d, u64 a, u64 b) {
    asm("fma.rn.f32x2 %0, %1, %2, %0;" : "+l"(d) : "l"(a), "l"(b));
}
__device__ __forceinline__ float2 unpack2(u64 v) {
    float2 f;
    asm("mov.b64 {%0, %1}, %2;" : "=f"(f.x), "=f"(f.y) : "l"(v));
    return f;
}
__device__ __forceinline__ void cp_async16(uint32_t saddr, const void* g) {
    asm volatile("cp.async.cg.shared.global [%0], [%1], 16;" ::
                 "r"(saddr), "l"(g));
}
__device__ __forceinline__ void cp_async4(uint32_t saddr, const void* g,
                                          bool ok) {
    int sz = ok ? 4 : 0;
    asm volatile("cp.async.ca.shared.global [%0], [%1], 4, %2;" ::
                 "r"(saddr), "l"(g), "r"(sz));
}

// Scratch (device globals: allocation-free, graph-capture safe).
__device__ float g_t1[134217728];       // 512 MB  (conv1 outputs, 64ch)
__device__ float g_t2[67108864];        // 256 MB  (conv2 outputs, 32ch)
__device__ float g_msf[2097152];        // 8 MB    (2 x 1024 x 1024)
// Transposed weights: w1t[unit][k(81)][co(64)], w2t[unit][ci(64)][k(25)][co(32)]
__device__ float g_w1t[NUM_UNITS * 81 * 64];
__device__ float g_w2t[NUM_UNITS * 64 * 25 * 32];

// ---------------------------------------------------------------------------
// Weight transpose prep (tiny, once per launch).
// ---------------------------------------------------------------------------
__global__ void prep_weights(const float* __restrict__ w1,
                             const float* __restrict__ w2) {
    const int n1 = NUM_UNITS * 64 * 81;
    for (int i = blockIdx.x * blockDim.x + threadIdx.x; i < n1;
         i += gridDim.x * blockDim.x) {
        int unit = i / 5184;
        int r = i - unit * 5184;
        int co = r / 81;
        int k = r - co * 81;
        g_w1t[unit * 5184 + k * 64 + co] = w1[i];
    }
    const int n2 = NUM_UNITS * 32 * 64 * 25;
    for (int i = blockIdx.x * blockDim.x + threadIdx.x; i < n2;
         i += gridDim.x * blockDim.x) {
        int unit = i / 51200;
        int r = i - unit * 51200;
        int co = r / 1600;
        int r2 = r - co * 1600;
        int ci = r2 / 25;
        int k = r2 - ci * 25;
        g_w2t[((unit * 64 + ci) * 25 + k) * 32 + co] = w2[i];
    }
}

// ---------------------------------------------------------------------------
// conv1: 9x9, 1->64, bias, relu. grid (W/16, H/16, B*numUnits), 256 threads.
// Each thread: 16 output channels (8 packed pairs) x 4 consecutive x pixels.
// ---------------------------------------------------------------------------
__global__ __launch_bounds__(256) void conv1_kernel(
    const float* __restrict__ in, int fromMsf, const float* __restrict__ b1,
    int H, int W, int B, int unitBase) {
    __shared__ float s_in[24 * 24];
    __shared__ float s_w[81 * 64];
    __shared__ float s_b[64];

    int tid = threadIdx.x;
    int bz = blockIdx.z;
    int b = bz % B, uu = bz / B;
    int unit = unitBase + uu;

    const float* gin = (fromMsf ? g_msf : in) + (size_t)b * H * W;
    const float* gw = g_w1t + (size_t)unit * 5184;

    for (int i = tid; i < 5184; i += 256) s_w[i] = gw[i];
    if (tid < 64) s_b[tid] = b1[unit * 64 + tid];

    int bx0 = blockIdx.x * 16 - 4, by0 = blockIdx.y * 16 - 4;
    for (int i = tid; i < 576; i += 256) {
        int iy = i / 24, ix = i - iy * 24;
        int gy = by0 + iy, gx = bx0 + ix;
        float v = 0.f;
        if ((unsigned)gy < (unsigned)H && (unsigned)gx < (unsigned)W)
            v = gin[(size_t)gy * W + gx];
        s_in[i] = v;
    }
    __syncthreads();

    int cg = tid >> 6;                 // 0..3 -> co base cg*16
    int pg = tid & 63;
    int py = pg >> 2;                  // 0..15
    int x0 = (pg & 3) << 2;            // 0,4,8,12

    u64 acc2[8][4];
#pragma unroll
    for (int j = 0; j < 8; j++)
#pragma unroll
        for (int p = 0; p < 4; p++) acc2[j][p] = 0ull;

#pragma unroll 1
    for (int ky = 0; ky < 9; ky++) {
        const float* row = s_in + (py + ky) * 24 + x0;
        float4 a = *(const float4*)row;
        float4 c = *(const float4*)(row + 4);
        float4 d = *(const float4*)(row + 8);
        float in12[12] = {a.x, a.y, a.z, a.w, c.x, c.y,
                          c.z, c.w, d.x, d.y, d.z, d.w};
        u64 dup[12];
#pragma unroll
        for (int i = 0; i < 12; i++) dup[i] = pack_dup(in12[i]);
#pragma unroll
        for (int kx = 0; kx < 9; kx++) {
            const float* wb = s_w + (ky * 9 + kx) * 64 + cg * 16;
            ulonglong2 wA = *(const ulonglong2*)(wb);
            ulonglong2 wB = *(const ulonglong2*)(wb + 4);
            ulonglong2 wC = *(const ulonglong2*)(wb + 8);
            ulonglong2 wD = *(const ulonglong2*)(wb + 12);
            u64 wp[8] = {wA.x, wA.y, wB.x, wB.y, wC.x, wC.y, wD.x, wD.y};
#pragma unroll
            for (int p = 0; p < 4; p++) {
                u64 iv = dup[kx + p];
#pragma unroll
                for (int j = 0; j < 8; j++) ffma2(acc2[j][p], wp[j], iv);
            }
        }
    }

    size_t HW = (size_t)H * W;
    int y = blockIdx.y * 16 + py, x = blockIdx.x * 16 + x0;
    float* gout = g_t1 + (size_t)(uu * B + b) * 64 * HW;
#pragma unroll
    for (int j = 0; j < 8; j++) {
        int co0 = cg * 16 + 2 * j;
        float b0 = s_b[co0], b1v = s_b[co0 + 1];
        float2 v0 = unpack2(acc2[j][0]);
        float2 v1 = unpack2(acc2[j][1]);
        float2 v2 = unpack2(acc2[j][2]);
        float2 v3 = unpack2(acc2[j][3]);
        float4 oA = {fmaxf(v0.x + b0, 0.f), fmaxf(v1.x + b0, 0.f),
                     fmaxf(v2.x + b0, 0.f), fmaxf(v3.x + b0, 0.f)};
        float4 oB = {fmaxf(v0.y + b1v, 0.f), fmaxf(v1.y + b1v, 0.f),
                     fmaxf(v2.y + b1v, 0.f), fmaxf(v3.y + b1v, 0.f)};
        *(float4*)(gout + (size_t)co0 * HW + (size_t)y * W + x) = oA;
        *(float4*)(gout + (size_t)(co0 + 1) * HW + (size_t)y * W + x) = oB;
    }
}

// ---------------------------------------------------------------------------
// conv2: 5x5, 64->32, bias, relu. grid (W/16, H/16, B*numUnits), 256 threads.
// Each thread: 8 output channels (4 packed pairs) x 4 consecutive x pixels.
// ci in 16 chunks of 4, double-buffered via cp.async: fill of chunk cc+1
// overlaps compute of chunk cc.
// ---------------------------------------------------------------------------
__global__ __launch_bounds__(256) void conv2_kernel(
    const float* __restrict__ b2, int H, int W, int B, int unitBase) {
    __shared__ float s_in[2][4 * 400];      // [buf][ci(4)][20][20]
    __shared__ float s_w[2][4 * 25 * 32];   // [buf][ci(4)][k][co]

    int tid = threadIdx.x;
    int bz = blockIdx.z;
    int b = bz % B, uu = bz / B;
    int unit = unitBase + uu;

    int cg = tid >> 6;                  // 0..3 -> co base cg*8
    int pg = tid & 63;
    int py = pg >> 2;                   // 0..15
    int x0 = (pg & 3) << 2;             // 0,4,8,12
    int bx0 = blockIdx.x * 16 - 2, by0 = blockIdx.y * 16 - 2;

    size_t HW = (size_t)H * W;
    const float* gin = g_t1 + (size_t)(uu * B + b) * 64 * HW;
    const float* gw = g_w2t + (size_t)unit * 51200;

    uint32_t sw_base0 = (uint32_t)__cvta_generic_to_shared(&s_w[0][0]);
    uint32_t sw_base1 = (uint32_t)__cvta_generic_to_shared(&s_w[1][0]);
    uint32_t si_base0 = (uint32_t)__cvta_generic_to_shared(&s_in[0][0]);
    uint32_t si_base1 = (uint32_t)__cvta_generic_to_shared(&s_in[1][0]);

    u64 acc2[4][4];
#pragma unroll
    for (int j = 0; j < 4; j++)
#pragma unroll
        for (int p = 0; p < 4; p++) acc2[j][p] = 0ull;

    // ---- issue fill of chunk cc into buffer cc&1 ----
    auto issue = [&](int cc) {
        int buf = cc & 1;
        uint32_t swb = buf ? sw_base1 : sw_base0;
        uint32_t sib = buf ? si_base1 : si_base0;
        const float* wsrc = gw + cc * 3200;
        for (int i = tid * 4; i < 3200; i += 1024)
            cp_async16(swb + i * 4, wsrc + i);
        for (int i = tid; i < 1600; i += 256) {
            int ci = i / 400;
            int r = i - ci * 400;
            int iy = r / 20, ix = r - iy * 20;
            int gy = by0 + iy, gx = bx0 + ix;
            bool ok = (unsigned)gy < (unsigned)H && (unsigned)gx < (unsigned)W;
            const float* src = gin + (size_t)(cc * 4 + ci) * HW +
                               (ok ? ((size_t)gy * W + gx) : 0);
            cp_async4(sib + i * 4, src, ok);
        }
        asm volatile("cp.async.commit_group;");
    };

    issue(0);
#pragma unroll 1
    for (int cc = 0; cc < 16; cc++) {
        if (cc + 1 < 16) {
            issue(cc + 1);
            asm volatile("cp.async.wait_group 1;");
        } else {
            asm volatile("cp.async.wait_group 0;");
        }
        __syncthreads();

        int buf = cc & 1;
        const float* sin_b = &s_in[buf][0];
        const float* sw_b = &s_w[buf][0];
#pragma unroll
        for (int ci = 0; ci < 4; ci++) {
            const float* rowbase = sin_b + ci * 400 + py * 20 + x0;
            const float* wci = sw_b + ci * 25 * 32 + cg * 8;
#pragma unroll
            for (int ky = 0; ky < 5; ky++) {
                float4 ia = *(const float4*)(rowbase + ky * 20);
                float4 ib = *(const float4*)(rowbase + ky * 20 + 4);
                float in8[8] = {ia.x, ia.y, ia.z, ia.w,
                                ib.x, ib.y, ib.z, ib.w};
                u64 dup[8];
#pragma unroll
                for (int i = 0; i < 8; i++) dup[i] = pack_dup(in8[i]);
                const float* wb = wci + ky * 5 * 32;
#pragma unroll
                for (int kx = 0; kx < 5; kx++) {
                    ulonglong2 wl = *(const ulonglong2*)(wb + kx * 32);
                    ulonglong2 wh = *(const ulonglong2*)(wb + kx * 32 + 4);
                    u64 wp[4] = {wl.x, wl.y, wh.x, wh.y};
#pragma unroll
                    for (int p = 0; p < 4; p++) {
                        u64 iv = dup[kx + p];
#pragma unroll
                        for (int j = 0; j < 4; j++)
                            ffma2(acc2[j][p], wp[j], iv);
                    }
                }
            }
        }
        __syncthreads();
    }

    int y = blockIdx.y * 16 + py, x = blockIdx.x * 16 + x0;
    float* gout = g_t2 + (size_t)(uu * B + b) * 32 * HW;
#pragma unroll
    for (int j = 0; j < 4; j++) {
        int co0 = cg * 8 + 2 * j;
        float b0 = b2[unit * 32 + co0], b1v = b2[unit * 32 + co0 + 1];
        float2 v0 = unpack2(acc2[j][0]);
        float2 v1 = unpack2(acc2[j][1]);
        float2 v2 = unpack2(acc2[j][2]);
        float2 v3 = unpack2(acc2[j][3]);
        float4 oA = {fmaxf(v0.x + b0, 0.f), fmaxf(v1.x + b0, 0.f),
                     fmaxf(v2.x + b0, 0.f), fmaxf(v3.x + b0, 0.f)};
        float4 oB = {fmaxf(v0.y + b1v, 0.f), fmaxf(v1.y + b1v, 0.f),
                     fmaxf(v2.y + b1v, 0.f), fmaxf(v3.y + b1v, 0.f)};
        *(float4*)(gout + (size_t)co0 * HW + (size_t)y * W + x) = oA;
        *(float4*)(gout + (size_t)(co0 + 1) * HW + (size_t)y * W + x) = oB;
    }
}

// ---------------------------------------------------------------------------
// conv3: 5x5, 32->1, bias. Writes interleaved (stage) or plain (MSF).
// ---------------------------------------------------------------------------
__global__ __launch_bounds__(256) void conv3_kernel(
    const float* __restrict__ w3, const float* __restrict__ b3,
    float* __restrict__ out, int H, int W, int B, int unitBase,
    int interleave) {
    __shared__ float s_in[16 * 400];
    __shared__ float s_w[16 * 25];

    int tx = threadIdx.x, ty = threadIdx.y;
    int tid = ty * 16 + tx;
    int bz = blockIdx.z;
    int b = bz % B, uu = bz / B;
    int unit = unitBase + uu;

    size_t HW = (size_t)H * W;
    const float* gin = g_t2 + (size_t)(uu * B + b) * 32 * HW;
    const float* gw = w3 + (size_t)unit * 800;  // [ci(32)][5][5]
    int bx0 = blockIdx.x * 16 - 2, by0 = blockIdx.y * 16 - 2;

    float acc = 0.f;
    for (int cc = 0; cc < 2; cc++) {
        __syncthreads();
        for (int i = tid; i < 16 * 400; i += 256) {
            int ci = i / 400;
            int r = i - ci * 400;
            int iy = r / 20, ix = r - iy * 20;
            int gy = by0 + iy, gx = bx0 + ix;
            float v = 0.f;
            if ((unsigned)gy < (unsigned)H && (unsigned)gx < (unsigned)W)
                v = gin[(size_t)(cc * 16 + ci) * HW + (size_t)gy * W + gx];
            s_in[i] = v;
        }
        for (int i = tid; i < 400; i += 256) s_w[i] = gw[cc * 400 + i];
        __syncthreads();

#pragma unroll 1
        for (int ci = 0; ci < 16; ci++) {
#pragma unroll
            for (int ky = 0; ky < 5; ky++)
#pragma unroll
                for (int kx = 0; kx < 5; kx++)
                    acc += s_in[ci * 400 + (ty + ky) * 20 + tx + kx] *
                           s_w[ci * 25 + ky * 5 + kx];
        }
    }
    acc += b3[unit];

    int y = blockIdx.y * 16 + ty, x = blockIdx.x * 16 + tx;
    if (interleave) {
        int dy = uu >> 1, dx = uu & 1;
        out[(size_t)b * 4 * HW + (size_t)(2 * y + dy) * (2 * W) +
            (2 * x + dx)] = acc;
    } else {
        out[(size_t)b * HW + (size_t)y * W + x] = acc;
    }
}

// ---------------------------------------------------------------------------
// MSF input: bilinear upscales (half-pixel, edge-clamped) + x16.
// ---------------------------------------------------------------------------
__device__ __forceinline__ float bilin(const float* __restrict__ p, int b,
                                       int H, int W, int oy, int ox, int s) {
    float sy = (oy + 0.5f) / (float)s - 0.5f;
    float sx = (ox + 0.5f) / (float)s - 0.5f;
    int y0 = (int)floorf(sy), x0 = (int)floorf(sx);
    float fy = sy - (float)y0, fx = sx - (float)x0;
    int y0c = min(max(y0, 0), H - 1), y1c = min(max(y0 + 1, 0), H - 1);
    int x0c = min(max(x0, 0), W - 1), x1c = min(max(x0 + 1, 0), W - 1);
    const float* pb = p + (size_t)b * H * W;
    float v00 = pb[(size_t)y0c * W + x0c];
    float v01 = pb[(size_t)y0c * W + x1c];
    float v10 = pb[(size_t)y1c * W + x0c];
    float v11 = pb[(size_t)y1c * W + x1c];
    return (1.f - fy) * ((1.f - fx) * v00 + fx * v01) +
           fy * ((1.f - fx) * v10 + fx * v11);
}

__global__ void msf_in_kernel(const float* __restrict__ x2,
                              const float* __restrict__ x4,
                              const float* __restrict__ x8,
                              const float* __restrict__ x16) {
    int idx = blockIdx.x * blockDim.x + threadIdx.x;
    if (idx >= 2 * 1024 * 1024) return;
    int b = idx >> 20;
    int r = idx & ((1 << 20) - 1);
    int y = r >> 10, x = r & 1023;
    float v = x16[idx];
    v += bilin(x2, b, 128, 128, y, x, 8);
    v += bilin(x4, b, 256, 256, y, x, 4);
    v += bilin(x8, b, 512, 512, y, x, 2);
    g_msf[idx] = v;
}

// ---------------------------------------------------------------------------
// Launch
// ---------------------------------------------------------------------------
extern "C" void kernel_launch(void* const* d_in, const int* in_sizes, int n_in,
                              void* d_out, int out_size) {
    const float* image = (const float*)d_in[0];
    const float* w1 = (const float*)d_in[1];
    const float* b1 = (const float*)d_in[2];
    const float* w2 = (const float*)d_in[3];
    const float* b2 = (const float*)d_in[4];
    const float* w3 = (const float*)d_in[5];
    const float* b3 = (const float*)d_in[6];
    float* out = (float*)d_out;

    float* o_x2 = out;                // 2*128*128  = 32768
    float* o_x4 = out + 32768;        // 2*256*256  = 131072
    float* o_x8 = out + 163840;       // 2*512*512  = 524288
    float* o_x16 = out + 688128;      // 2*1024*1024 = 2097152
    float* o_msf = out + 2785280;     // 2*1024*1024 = 2097152
    const int B = 2;

    prep_weights<<<256, 256>>>(w1, w2);

    const float* sin[4] = {image, o_x2, o_x4, o_x8};
    float* sout[4] = {o_x2, o_x4, o_x8, o_x16};
    int sH[4] = {64, 128, 256, 512};
    for (int s = 0; s < 4; s++) {
        int H = sH[s], W = sH[s];
        int ub = s * 4;
        dim3 grid(W / 16, H / 16, B * 4);
        conv1_kernel<<<grid, 256>>>(sin[s], 0, b1, H, W, B, ub);
        conv2_kernel<<<grid, 256>>>(b2, H, W, B, ub);
        conv3_kernel<<<grid, dim3(16, 16)>>>(w3, b3, sout[s], H, W, B, ub, 1);
    }

    msf_in_kernel<<<(2 * 1024 * 1024) / 256, 256>>>(o_x2, o_x4, o_x8, o_x16);
    {
        int H = 1024, W = 1024;
        dim3 grid(W / 16, H / 16, B * 1);
        conv1_kernel<<<grid, 256>>>(nullptr, 1, b1, H, W, B, 16);
        conv2_kernel<<<grid, 256>>>(b2, H, W, B, 16);
        conv3_kernel<<<grid, dim3(16, 16)>>>(w3, b3, o_msf, H, W, B, 16, 0);
    }
}

// round 14
// speedup vs baseline: 1.2502x; 1.0653x over previous
#include <cuda_runtime.h>
#include <stdint.h>
#include <math.h>

// ---------------------------------------------------------------------------
// DSDMSR: 4 stages of 4 SRCNN units (interleaved 2x upscale each) + MSF unit.
// Round 14 (= Round 8 kernel, seventh submission; broker timeouts R8-R13):
// conv2 widened to 8 px/thread (32x16 tile) to halve weight-LDS per FFMA2
// (suspected LSU/crossbar bound), keeping FFMA2 + cp.async pipeline.
// ---------------------------------------------------------------------------

#define NUM_UNITS 17

typedef unsigned long long u64;

__device__ __forceinline__ u64 pack_dup(float v) {
    u64 r;
    asm("mov.b64 %0, {%1, %2};" : "=l"(r) : "f"(v), "f"(v));
    return r;
}
__device__ __forceinline__ void ffma2(u64& d, u64 a, u64 b) {
    asm("fma.rn.f32x2 %0, %1, %2, %0;" : "+l"(d) : "l"(a), "l"(b));
}
__device__ __forceinline__ float2 unpack2(u64 v) {
    float2 f;
    asm("mov.b64 {%0, %1}, %2;" : "=f"(f.x), "=f"(f.y) : "l"(v));
    return f;
}
__device__ __forceinline__ void cp_async16(uint32_t saddr, const void* g) {
    asm volatile("cp.async.cg.shared.global [%0], [%1], 16;" ::
                 "r"(saddr), "l"(g));
}
__device__ __forceinline__ void cp_async4(uint32_t saddr, const void* g,
                                          bool ok) {
    int sz = ok ? 4 : 0;
    asm volatile("cp.async.ca.shared.global [%0], [%1], 4, %2;" ::
                 "r"(saddr), "l"(g), "r"(sz));
}

// Scratch (device globals: allocation-free, graph-capture safe).
__device__ float g_t1[134217728];       // 512 MB  (conv1 outputs, 64ch)
__device__ float g_t2[67108864];        // 256 MB  (conv2 outputs, 32ch)
__device__ float g_msf[2097152];        // 8 MB    (2 x 1024 x 1024)
__device__ float g_w1t[NUM_UNITS * 81 * 64];
__device__ float g_w2t[NUM_UNITS * 64 * 25 * 32];

// ---------------------------------------------------------------------------
// Weight transpose prep.
// ---------------------------------------------------------------------------
__global__ void prep_weights(const float* __restrict__ w1,
                             const float* __restrict__ w2) {
    const int n1 = NUM_UNITS * 64 * 81;
    for (int i = blockIdx.x * blockDim.x + threadIdx.x; i < n1;
         i += gridDim.x * blockDim.x) {
        int unit = i / 5184;
        int r = i - unit * 5184;
        int co = r / 81;
        int k = r - co * 81;
        g_w1t[unit * 5184 + k * 64 + co] = w1[i];
    }
    const int n2 = NUM_UNITS * 32 * 64 * 25;
    for (int i = blockIdx.x * blockDim.x + threadIdx.x; i < n2;
         i += gridDim.x * blockDim.x) {
        int unit = i / 51200;
        int r = i - unit * 51200;
        int co = r / 1600;
        int r2 = r - co * 1600;
        int ci = r2 / 25;
        int k = r2 - ci * 25;
        g_w2t[((unit * 64 + ci) * 25 + k) * 32 + co] = w2[i];
    }
}

// ---------------------------------------------------------------------------
// conv1: 9x9, 1->64, bias, relu. (unchanged from R7 passing kernel)
// ---------------------------------------------------------------------------
__global__ __launch_bounds__(256) void conv1_kernel(
    const float* __restrict__ in, int fromMsf, const float* __restrict__ b1,
    int H, int W, int B, int unitBase) {
    __shared__ float s_in[24 * 24];
    __shared__ float s_w[81 * 64];
    __shared__ float s_b[64];

    int tid = threadIdx.x;
    int bz = blockIdx.z;
    int b = bz % B, uu = bz / B;
    int unit = unitBase + uu;

    const float* gin = (fromMsf ? g_msf : in) + (size_t)b * H * W;
    const float* gw = g_w1t + (size_t)unit * 5184;

    for (int i = tid; i < 5184; i += 256) s_w[i] = gw[i];
    if (tid < 64) s_b[tid] = b1[unit * 64 + tid];

    int bx0 = blockIdx.x * 16 - 4, by0 = blockIdx.y * 16 - 4;
    for (int i = tid; i < 576; i += 256) {
        int iy = i / 24, ix = i - iy * 24;
        int gy = by0 + iy, gx = bx0 + ix;
        float v = 0.f;
        if ((unsigned)gy < (unsigned)H && (unsigned)gx < (unsigned)W)
            v = gin[(size_t)gy * W + gx];
        s_in[i] = v;
    }
    __syncthreads();

    int cg = tid >> 6;
    int pg = tid & 63;
    int py = pg >> 2;
    int x0 = (pg & 3) << 2;

    u64 acc2[8][4];
#pragma unroll
    for (int j = 0; j < 8; j++)
#pragma unroll
        for (int p = 0; p < 4; p++) acc2[j][p] = 0ull;

#pragma unroll 1
    for (int ky = 0; ky < 9; ky++) {
        const float* row = s_in + (py + ky) * 24 + x0;
        float4 a = *(const float4*)row;
        float4 c = *(const float4*)(row + 4);
        float4 d = *(const float4*)(row + 8);
        float in12[12] = {a.x, a.y, a.z, a.w, c.x, c.y,
                          c.z, c.w, d.x, d.y, d.z, d.w};
        u64 dup[12];
#pragma unroll
        for (int i = 0; i < 12; i++) dup[i] = pack_dup(in12[i]);
#pragma unroll
        for (int kx = 0; kx < 9; kx++) {
            const float* wb = s_w + (ky * 9 + kx) * 64 + cg * 16;
            ulonglong2 wA = *(const ulonglong2*)(wb);
            ulonglong2 wB = *(const ulonglong2*)(wb + 4);
            ulonglong2 wC = *(const ulonglong2*)(wb + 8);
            ulonglong2 wD = *(const ulonglong2*)(wb + 12);
            u64 wp[8] = {wA.x, wA.y, wB.x, wB.y, wC.x, wC.y, wD.x, wD.y};
#pragma unroll
            for (int p = 0; p < 4; p++) {
                u64 iv = dup[kx + p];
#pragma unroll
                for (int j = 0; j < 8; j++) ffma2(acc2[j][p], wp[j], iv);
            }
        }
    }

    size_t HW = (size_t)H * W;
    int y = blockIdx.y * 16 + py, x = blockIdx.x * 16 + x0;
    float* gout = g_t1 + (size_t)(uu * B + b) * 64 * HW;
#pragma unroll
    for (int j = 0; j < 8; j++) {
        int co0 = cg * 16 + 2 * j;
        float b0 = s_b[co0], b1v = s_b[co0 + 1];
        float2 v0 = unpack2(acc2[j][0]);
        float2 v1 = unpack2(acc2[j][1]);
        float2 v2 = unpack2(acc2[j][2]);
        float2 v3 = unpack2(acc2[j][3]);
        float4 oA = {fmaxf(v0.x + b0, 0.f), fmaxf(v1.x + b0, 0.f),
                     fmaxf(v2.x + b0, 0.f), fmaxf(v3.x + b0, 0.f)};
        float4 oB = {fmaxf(v0.y + b1v, 0.f), fmaxf(v1.y + b1v, 0.f),
                     fmaxf(v2.y + b1v, 0.f), fmaxf(v3.y + b1v, 0.f)};
        *(float4*)(gout + (size_t)co0 * HW + (size_t)y * W + x) = oA;
        *(float4*)(gout + (size_t)(co0 + 1) * HW + (size_t)y * W + x) = oB;
    }
}

// ---------------------------------------------------------------------------
// conv2: 5x5, 64->32, bias, relu. grid (W/32, H/16, B*numUnits), 256 threads.
// Tile 32x16. Each thread: 8 co (4 packed pairs) x 8 consecutive x pixels.
// ci in 16 chunks of 4, double-buffered cp.async.
// Smem: (2880 + 3200) * 2 * 4B = 48640 B (< 48 KB static limit).
// ---------------------------------------------------------------------------
__global__ __launch_bounds__(256) void conv2_kernel(
    const float* __restrict__ b2, int H, int W, int B, int unitBase) {
    __shared__ float s_in[2][4 * 720];      // [buf][ci(4)][20][36]
    __shared__ float s_w[2][4 * 25 * 32];   // [buf][ci(4)][k][co]

    int tid = threadIdx.x;
    int bz = blockIdx.z;
    int b = bz % B, uu = bz / B;
    int unit = unitBase + uu;

    int cg = tid >> 6;                  // 0..3 -> co base cg*8
    int pg = tid & 63;
    int py = pg >> 2;                   // 0..15 (row in tile)
    int x0 = (pg & 3) << 3;             // 0,8,16,24
    int bx0 = blockIdx.x * 32 - 2, by0 = blockIdx.y * 16 - 2;

    size_t HW = (size_t)H * W;
    const float* gin = g_t1 + (size_t)(uu * B + b) * 64 * HW;
    const float* gw = g_w2t + (size_t)unit * 51200;

    uint32_t sw_base0 = (uint32_t)__cvta_generic_to_shared(&s_w[0][0]);
    uint32_t sw_base1 = (uint32_t)__cvta_generic_to_shared(&s_w[1][0]);
    uint32_t si_base0 = (uint32_t)__cvta_generic_to_shared(&s_in[0][0]);
    uint32_t si_base1 = (uint32_t)__cvta_generic_to_shared(&s_in[1][0]);

    u64 acc2[4][8];
#pragma unroll
    for (int j = 0; j < 4; j++)
#pragma unroll
        for (int p = 0; p < 8; p++) acc2[j][p] = 0ull;

    auto issue = [&](int cc) {
        int buf = cc & 1;
        uint32_t swb = buf ? sw_base1 : sw_base0;
        uint32_t sib = buf ? si_base1 : si_base0;
        const float* wsrc = gw + cc * 3200;
        for (int i = tid * 4; i < 3200; i += 1024)
            cp_async16(swb + i * 4, wsrc + i);
        for (int i = tid; i < 2880; i += 256) {
            int ci = i / 720;
            int r = i - ci * 720;
            int iy = r / 36, ix = r - iy * 36;
            int gy = by0 + iy, gx = bx0 + ix;
            bool ok = (unsigned)gy < (unsigned)H && (unsigned)gx < (unsigned)W;
            const float* src = gin + (size_t)(cc * 4 + ci) * HW +
                               (ok ? ((size_t)gy * W + gx) : 0);
            cp_async4(sib + i * 4, src, ok);
        }
        asm volatile("cp.async.commit_group;");
    };

    issue(0);
#pragma unroll 1
    for (int cc = 0; cc < 16; cc++) {
        if (cc + 1 < 16) {
            issue(cc + 1);
            asm volatile("cp.async.wait_group 1;");
        } else {
            asm volatile("cp.async.wait_group 0;");
        }
        __syncthreads();

        int buf = cc & 1;
        const float* sin_b = &s_in[buf][0];
        const float* sw_b = &s_w[buf][0];
#pragma unroll
        for (int ci = 0; ci < 4; ci++) {
            const float* rowbase = sin_b + ci * 720 + py * 36 + x0;
            const float* wci = sw_b + ci * 25 * 32 + cg * 8;
#pragma unroll
            for (int ky = 0; ky < 5; ky++) {
                const float* row = rowbase + ky * 36;
                float4 ia = *(const float4*)row;
                float4 ib = *(const float4*)(row + 4);
                float4 ic = *(const float4*)(row + 8);
                float in12[12] = {ia.x, ia.y, ia.z, ia.w, ib.x, ib.y,
                                  ib.z, ib.w, ic.x, ic.y, ic.z, ic.w};
                u64 dup[12];
#pragma unroll
                for (int i = 0; i < 12; i++) dup[i] = pack_dup(in12[i]);
                const float* wb = wci + ky * 5 * 32;
#pragma unroll
                for (int kx = 0; kx < 5; kx++) {
                    ulonglong2 wl = *(const ulonglong2*)(wb + kx * 32);
                    ulonglong2 wh = *(const ulonglong2*)(wb + kx * 32 + 4);
                    u64 wp[4] = {wl.x, wl.y, wh.x, wh.y};
#pragma unroll
                    for (int p = 0; p < 8; p++) {
                        u64 iv = dup[kx + p];
#pragma unroll
                        for (int j = 0; j < 4; j++)
                            ffma2(acc2[j][p], wp[j], iv);
                    }
                }
            }
        }
        __syncthreads();
    }

    int y = blockIdx.y * 16 + py, x = blockIdx.x * 32 + x0;
    float* gout = g_t2 + (size_t)(uu * B + b) * 32 * HW;
#pragma unroll
    for (int j = 0; j < 4; j++) {
        int co0 = cg * 8 + 2 * j;
        float b0 = b2[unit * 32 + co0], b1v = b2[unit * 32 + co0 + 1];
        float2 v[8];
#pragma unroll
        for (int p = 0; p < 8; p++) v[p] = unpack2(acc2[j][p]);
        float4 oA0 = {fmaxf(v[0].x + b0, 0.f), fmaxf(v[1].x + b0, 0.f),
                      fmaxf(v[2].x + b0, 0.f), fmaxf(v[3].x + b0, 0.f)};
        float4 oA1 = {fmaxf(v[4].x + b0, 0.f), fmaxf(v[5].x + b0, 0.f),
                      fmaxf(v[6].x + b0, 0.f), fmaxf(v[7].x + b0, 0.f)};
        float4 oB0 = {fmaxf(v[0].y + b1v, 0.f), fmaxf(v[1].y + b1v, 0.f),
                      fmaxf(v[2].y + b1v, 0.f), fmaxf(v[3].y + b1v, 0.f)};
        float4 oB1 = {fmaxf(v[4].y + b1v, 0.f), fmaxf(v[5].y + b1v, 0.f),
                      fmaxf(v[6].y + b1v, 0.f), fmaxf(v[7].y + b1v, 0.f)};
        float* p0 = gout + (size_t)co0 * HW + (size_t)y * W + x;
        float* p1 = gout + (size_t)(co0 + 1) * HW + (size_t)y * W + x;
        *(float4*)p0 = oA0;
        *(float4*)(p0 + 4) = oA1;
        *(float4*)p1 = oB0;
        *(float4*)(p1 + 4) = oB1;
    }
}

// ---------------------------------------------------------------------------
// conv3: 5x5, 32->1, bias. (unchanged)
// ---------------------------------------------------------------------------
__global__ __launch_bounds__(256) void conv3_kernel(
    const float* __restrict__ w3, const float* __restrict__ b3,
    float* __restrict__ out, int H, int W, int B, int unitBase,
    int interleave) {
    __shared__ float s_in[16 * 400];
    __shared__ float s_w[16 * 25];

    int tx = threadIdx.x, ty = threadIdx.y;
    int tid = ty * 16 + tx;
    int bz = blockIdx.z;
    int b = bz % B, uu = bz / B;
    int unit = unitBase + uu;

    size_t HW = (size_t)H * W;
    const float* gin = g_t2 + (size_t)(uu * B + b) * 32 * HW;
    const float* gw = w3 + (size_t)unit * 800;
    int bx0 = blockIdx.x * 16 - 2, by0 = blockIdx.y * 16 - 2;

    float acc = 0.f;
    for (int cc = 0; cc < 2; cc++) {
        __syncthreads();
        for (int i = tid; i < 16 * 400; i += 256) {
            int ci = i / 400;
            int r = i - ci * 400;
            int iy = r / 20, ix = r - iy * 20;
            int gy = by0 + iy, gx = bx0 + ix;
            float v = 0.f;
            if ((unsigned)gy < (unsigned)H && (unsigned)gx < (unsigned)W)
                v = gin[(size_t)(cc * 16 + ci) * HW + (size_t)gy * W + gx];
            s_in[i] = v;
        }
        for (int i = tid; i < 400; i += 256) s_w[i] = gw[cc * 400 + i];
        __syncthreads();

#pragma unroll 1
        for (int ci = 0; ci < 16; ci++) {
#pragma unroll
            for (int ky = 0; ky < 5; ky++)
#pragma unroll
                for (int kx = 0; kx < 5; kx++)
                    acc += s_in[ci * 400 + (ty + ky) * 20 + tx + kx] *
                           s_w[ci * 25 + ky * 5 + kx];
        }
    }
    acc += b3[unit];

    int y = blockIdx.y * 16 + ty, x = blockIdx.x * 16 + tx;
    if (interleave) {
        int dy = uu >> 1, dx = uu & 1;
        out[(size_t)b * 4 * HW + (size_t)(2 * y + dy) * (2 * W) +
            (2 * x + dx)] = acc;
    } else {
        out[(size_t)b * HW + (size_t)y * W + x] = acc;
    }
}

// ---------------------------------------------------------------------------
// MSF input: bilinear upscales (half-pixel, edge-clamped) + x16.
// ---------------------------------------------------------------------------
__device__ __forceinline__ float bilin(const float* __restrict__ p, int b,
                                       int H, int W, int oy, int ox, int s) {
    float sy = (oy + 0.5f) / (float)s - 0.5f;
    float sx = (ox + 0.5f) / (float)s - 0.5f;
    int y0 = (int)floorf(sy), x0 = (int)floorf(sx);
    float fy = sy - (float)y0, fx = sx - (float)x0;
    int y0c = min(max(y0, 0), H - 1), y1c = min(max(y0 + 1, 0), H - 1);
    int x0c = min(max(x0, 0), W - 1), x1c = min(max(x0 + 1, 0), W - 1);
    const float* pb = p + (size_t)b * H * W;
    float v00 = pb[(size_t)y0c * W + x0c];
    float v01 = pb[(size_t)y0c * W + x1c];
    float v10 = pb[(size_t)y1c * W + x0c];
    float v11 = pb[(size_t)y1c * W + x1c];
    return (1.f - fy) * ((1.f - fx) * v00 + fx * v01) +
           fy * ((1.f - fx) * v10 + fx * v11);
}

__global__ void msf_in_kernel(const float* __restrict__ x2,
                              const float* __restrict__ x4,
                              const float* __restrict__ x8,
                              const float* __restrict__ x16) {
    int idx = blockIdx.x * blockDim.x + threadIdx.x;
    if (idx >= 2 * 1024 * 1024) return;
    int b = idx >> 20;
    int r = idx & ((1 << 20) - 1);
    int y = r >> 10, x = r & 1023;
    float v = x16[idx];
    v += bilin(x2, b, 128, 128, y, x, 8);
    v += bilin(x4, b, 256, 256, y, x, 4);
    v += bilin(x8, b, 512, 512, y, x, 2);
    g_msf[idx] = v;
}

// ---------------------------------------------------------------------------
// Launch
// ---------------------------------------------------------------------------
extern "C" void kernel_launch(void* const* d_in, const int* in_sizes, int n_in,
                              void* d_out, int out_size) {
    const float* image = (const float*)d_in[0];
    const float* w1 = (const float*)d_in[1];
    const float* b1 = (const float*)d_in[2];
    const float* w2 = (const float*)d_in[3];
    const float* b2 = (const float*)d_in[4];
    const float* w3 = (const float*)d_in[5];
    const float* b3 = (const float*)d_in[6];
    float* out = (float*)d_out;

    float* o_x2 = out;                // 2*128*128  = 32768
    float* o_x4 = out + 32768;        // 2*256*256  = 131072
    float* o_x8 = out + 163840;       // 2*512*512  = 524288
    float* o_x16 = out + 688128;      // 2*1024*1024 = 2097152
    float* o_msf = out + 2785280;     // 2*1024*1024 = 2097152
    const int B = 2;

    prep_weights<<<256, 256>>>(w1, w2);

    const float* sin[4] = {image, o_x2, o_x4, o_x8};
    float* sout[4] = {o_x2, o_x4, o_x8, o_x16};
    int sH[4] = {64, 128, 256, 512};
    for (int s = 0; s < 4; s++) {
        int H = sH[s], W = sH[s];
        int ub = s * 4;
        dim3 grid1(W / 16, H / 16, B * 4);
        dim3 grid2(W / 32, H / 16, B * 4);
        conv1_kernel<<<grid1, 256>>>(sin[s], 0, b1, H, W, B, ub);
        conv2_kernel<<<grid2, 256>>>(b2, H, W, B, ub);
        conv3_kernel<<<grid1, dim3(16, 16)>>>(w3, b3, sout[s], H, W, B, ub, 1);
    }

    msf_in_kernel<<<(2 * 1024 * 1024) / 256, 256>>>(o_x2, o_x4, o_x8, o_x16);
    {
        int H = 1024, W = 1024;
        dim3 grid1(W / 16, H / 16, B * 1);
        dim3 grid2(W / 32, H / 16, B * 1);
        conv1_kernel<<<grid1, 256>>>(nullptr, 1, b1, H, W, B, 16);
        conv2_kernel<<<grid2, 256>>>(b2, H, W, B, 16);
        conv3_kernel<<<grid1, dim3(16, 16)>>>(w3, b3, o_msf, H, W, B, 16, 0);
    }
}

// round 17
// speedup vs baseline: 1.7940x; 1.4350x over previous
#include <cuda_runtime.h>
#include <cuda_bf16.h>
#include <stdint.h>
#include <math.h>

// ---------------------------------------------------------------------------
// DSDMSR. Round 17: conv2 via mma.sync m16n8k16 bf16 (hi/lo split).
// Fix vs R16: weight tiles stored k-major [ci][co] (ldmatrix.trans delivers
// B[k=2t][n=g] as required); bank-conflict-free chunk swizzle nn^((ci>>1)&3).
// ---------------------------------------------------------------------------

#define NUM_UNITS 17
typedef unsigned long long u64;
typedef unsigned short ushort_t;

__device__ __forceinline__ u64 pack_dup(float v) {
    u64 r; asm("mov.b64 %0, {%1, %2};" : "=l"(r) : "f"(v), "f"(v)); return r;
}
__device__ __forceinline__ void ffma2(u64& d, u64 a, u64 b) {
    asm("fma.rn.f32x2 %0, %1, %2, %0;" : "+l"(d) : "l"(a), "l"(b));
}
__device__ __forceinline__ float2 unpack2(u64 v) {
    float2 f; asm("mov.b64 {%0, %1}, %2;" : "=f"(f.x), "=f"(f.y) : "l"(v)); return f;
}
__device__ __forceinline__ void cp_async16(uint32_t saddr, const void* g) {
    asm volatile("cp.async.cg.shared.global [%0], [%1], 16;" :: "r"(saddr), "l"(g));
}
__device__ __forceinline__ void cp_async16z(uint32_t saddr, const void* g, bool ok) {
    int sz = ok ? 16 : 0;
    asm volatile("cp.async.cg.shared.global [%0], [%1], 16, %2;" ::
                 "r"(saddr), "l"(g), "r"(sz));
}
__device__ __forceinline__ uint32_t smem_u32(const void* p) {
    uint32_t a;
    asm("{ .reg .u64 t; cvta.to.shared.u64 t, %1; cvt.u32.u64 %0, t; }"
        : "=r"(a) : "l"(p));
    return a;
}
__device__ __forceinline__ void ldsm_x4(uint32_t a[4], uint32_t addr) {
    asm volatile("ldmatrix.sync.aligned.m8n8.x4.shared.b16 {%0,%1,%2,%3}, [%4];"
                 : "=r"(a[0]), "=r"(a[1]), "=r"(a[2]), "=r"(a[3]) : "r"(addr));
}
__device__ __forceinline__ void ldsm_x2t(uint32_t b[2], uint32_t addr) {
    asm volatile("ldmatrix.sync.aligned.m8n8.x2.trans.shared.b16 {%0,%1}, [%2];"
                 : "=r"(b[0]), "=r"(b[1]) : "r"(addr));
}
__device__ __forceinline__ void mma16816(float c[4], const uint32_t a[4],
                                         const uint32_t b[2]) {
    asm volatile(
        "mma.sync.aligned.m16n8k16.row.col.f32.bf16.bf16.f32 "
        "{%0,%1,%2,%3}, {%4,%5,%6,%7}, {%8,%9}, {%0,%1,%2,%3};"
        : "+f"(c[0]), "+f"(c[1]), "+f"(c[2]), "+f"(c[3])
        : "r"(a[0]), "r"(a[1]), "r"(a[2]), "r"(a[3]), "r"(b[0]), "r"(b[1]));
}

// ---- scratch ----
__device__ ushort_t g_t1h[134217728];   // conv1 hi plane [img][y][x][ci]
__device__ ushort_t g_t1l[134217728];   // conv1 lo plane
__device__ float g_t2[67108864];        // conv2 out, planar f32
__device__ float g_msf[2097152];
__device__ float g_w1t[NUM_UNITS * 81 * 64];
// per (unit,tap): [ci(64)][co(32)] bf16, chunk-swizzled: 16B chunk nn stored
// at nn ^ ((ci>>1)&3)
__device__ ushort_t g_w2h[NUM_UNITS * 25 * 2048];
__device__ ushort_t g_w2l[NUM_UNITS * 25 * 2048];

__device__ __forceinline__ unsigned bf16_us(__nv_bfloat16 h) {
    return (unsigned)__bfloat16_as_ushort(h);
}

// ---------------------------------------------------------------------------
// prep: w1 transpose + w2 -> hi/lo bf16 k-major swizzled tap tiles
// ---------------------------------------------------------------------------
__global__ void prep_weights(const float* __restrict__ w1,
                             const float* __restrict__ w2) {
    const int n1 = NUM_UNITS * 64 * 81;
    for (int i = blockIdx.x * blockDim.x + threadIdx.x; i < n1;
         i += gridDim.x * blockDim.x) {
        int unit = i / 5184;
        int r = i - unit * 5184;
        int co = r / 81;
        int k = r - co * 81;
        g_w1t[unit * 5184 + k * 64 + co] = w1[i];
    }
    const int n2 = NUM_UNITS * 25 * 2048;
    for (int i = blockIdx.x * blockDim.x + threadIdx.x; i < n2;
         i += gridDim.x * blockDim.x) {
        int unit = i / 51200;
        int rr = i - unit * 51200;
        int tap = rr >> 11;
        int q2 = rr & 2047;
        int co = q2 >> 6, ci = q2 & 63;
        float v = w2[(size_t)unit * 51200 + co * 1600 + ci * 25 + tap];
        __nv_bfloat16 h = __float2bfloat16_rn(v);
        __nv_bfloat16 l = __float2bfloat16_rn(v - __bfloat162float(h));
        int nn = co >> 3;
        int idx = ci * 32 + ((nn ^ ((ci >> 1) & 3)) << 3) + (co & 7);
        size_t base = (size_t)(unit * 25 + tap) * 2048;
        g_w2h[base + idx] = __bfloat16_as_ushort(h);
        g_w2l[base + idx] = __bfloat16_as_ushort(l);
    }
}

// ---------------------------------------------------------------------------
// conv1: 9x9 1->64 relu (FFMA2); epilogue emits hi/lo bf16 planes [y][x][ci].
// ---------------------------------------------------------------------------
__global__ __launch_bounds__(256) void conv1_kernel(
    const float* __restrict__ in, int fromMsf, const float* __restrict__ b1,
    int H, int W, int B, int unitBase) {
    __shared__ float s_in[24 * 24];
    __shared__ float s_w[81 * 64];
    __shared__ float s_b[64];

    int tid = threadIdx.x;
    int bz = blockIdx.z;
    int b = bz % B, uu = bz / B;
    int unit = unitBase + uu;

    const float* gin = (fromMsf ? g_msf : in) + (size_t)b * H * W;
    const float* gw = g_w1t + (size_t)unit * 5184;

    for (int i = tid; i < 5184; i += 256) s_w[i] = gw[i];
    if (tid < 64) s_b[tid] = b1[unit * 64 + tid];

    int bx0 = blockIdx.x * 16 - 4, by0 = blockIdx.y * 16 - 4;
    for (int i = tid; i < 576; i += 256) {
        int iy = i / 24, ix = i - iy * 24;
        int gy = by0 + iy, gx = bx0 + ix;
        float v = 0.f;
        if ((unsigned)gy < (unsigned)H && (unsigned)gx < (unsigned)W)
            v = gin[(size_t)gy * W + gx];
        s_in[i] = v;
    }
    __syncthreads();

    int cg = tid >> 6;
    int pg = tid & 63;
    int py = pg >> 2;
    int x0 = (pg & 3) << 2;

    u64 acc2[8][4];
#pragma unroll
    for (int j = 0; j < 8; j++)
#pragma unroll
        for (int p = 0; p < 4; p++) acc2[j][p] = 0ull;

#pragma unroll 1
    for (int ky = 0; ky < 9; ky++) {
        const float* row = s_in + (py + ky) * 24 + x0;
        float4 a = *(const float4*)row;
        float4 c = *(const float4*)(row + 4);
        float4 d = *(const float4*)(row + 8);
        float in12[12] = {a.x, a.y, a.z, a.w, c.x, c.y,
                          c.z, c.w, d.x, d.y, d.z, d.w};
        u64 dup[12];
#pragma unroll
        for (int i = 0; i < 12; i++) dup[i] = pack_dup(in12[i]);
#pragma unroll
        for (int kx = 0; kx < 9; kx++) {
            const float* wb = s_w + (ky * 9 + kx) * 64 + cg * 16;
            ulonglong2 wA = *(const ulonglong2*)(wb);
            ulonglong2 wB = *(const ulonglong2*)(wb + 4);
            ulonglong2 wC = *(const ulonglong2*)(wb + 8);
            ulonglong2 wD = *(const ulonglong2*)(wb + 12);
            u64 wp[8] = {wA.x, wA.y, wB.x, wB.y, wC.x, wC.y, wD.x, wD.y};
#pragma unroll
            for (int p = 0; p < 4; p++) {
                u64 iv = dup[kx + p];
#pragma unroll
                for (int j = 0; j < 8; j++) ffma2(acc2[j][p], wp[j], iv);
            }
        }
    }

    size_t HW = (size_t)H * W;
    int y = blockIdx.y * 16 + py, xb = blockIdx.x * 16 + x0;
    size_t imgBase = (size_t)(uu * B + b) * HW * 64;
#pragma unroll
    for (int p = 0; p < 4; p++) {
        unsigned hp[8], lp[8];
#pragma unroll
        for (int j = 0; j < 8; j++) {
            int co0 = cg * 16 + 2 * j;
            float2 v = unpack2(acc2[j][p]);
            float a0 = fmaxf(v.x + s_b[co0], 0.f);
            float a1 = fmaxf(v.y + s_b[co0 + 1], 0.f);
            __nv_bfloat16 h0 = __float2bfloat16_rn(a0);
            __nv_bfloat16 h1 = __float2bfloat16_rn(a1);
            __nv_bfloat16 l0 = __float2bfloat16_rn(a0 - __bfloat162float(h0));
            __nv_bfloat16 l1 = __float2bfloat16_rn(a1 - __bfloat162float(h1));
            hp[j] = bf16_us(h0) | (bf16_us(h1) << 16);
            lp[j] = bf16_us(l0) | (bf16_us(l1) << 16);
        }
        size_t off = imgBase + ((size_t)y * W + xb + p) * 64 + cg * 16;
        uint4* dh = (uint4*)(g_t1h + off);
        uint4* dl = (uint4*)(g_t1l + off);
        dh[0] = make_uint4(hp[0], hp[1], hp[2], hp[3]);
        dh[1] = make_uint4(hp[4], hp[5], hp[6], hp[7]);
        dl[0] = make_uint4(lp[0], lp[1], lp[2], lp[3]);
        dl[1] = make_uint4(lp[4], lp[5], lp[6], lp[7]);
    }
}

// ---------------------------------------------------------------------------
// conv2 (mma.sync): 5x5 64->32 relu. grid (W/16, H/8, B*units), 256 threads.
// Warp w = tile row w (16 px = m). Pass0: Ah*Bh + Ah*Bl; pass1: Al*Bh.
// ---------------------------------------------------------------------------
__global__ __launch_bounds__(256) void conv2_mma_kernel(
    const float* __restrict__ b2, int H, int W, int B, int unitBase) {
    __shared__ __align__(16) ushort_t s_in[240 * 64];     // 30720 B
    __shared__ __align__(16) ushort_t s_w[2][4096];       // 16384 B
    __shared__ float s_bias[32];

    int tid = threadIdx.x;
    int wid = tid >> 5, lane = tid & 31;
    int bz = blockIdx.z;
    int b = bz % B, uu = bz / B;
    int unit = unitBase + uu;
    size_t HW = (size_t)H * W;

    const ushort_t* ginh = g_t1h + (size_t)(uu * B + b) * HW * 64;
    const ushort_t* ginl = g_t1l + (size_t)(uu * B + b) * HW * 64;
    const ushort_t* gwh = g_w2h + (size_t)unit * 25 * 2048;
    const ushort_t* gwl = g_w2l + (size_t)unit * 25 * 2048;

    uint32_t sinb = smem_u32(s_in);
    uint32_t swb = smem_u32(&s_w[0][0]);

    if (tid < 32) s_bias[tid] = b2[unit * 32 + tid];

    int y0 = blockIdx.y * 8, x0 = blockIdx.x * 16;

    // A fragment geometry (ldmatrix.x4 non-trans)
    int r = lane & 7, m = lane >> 3;
    int ax = ((m & 1) << 3) + r;   // A row (pixel col) 0..15
    int ach = m >> 1;              // k-octet select 0/1
    // B fragment geometry (ldmatrix.x2.trans over k-major [ci][co])
    int bro = lane & 15;           // ci row offset within 16-chunk
    int bsw = (bro >> 1) & 3;      // chunk swizzle for this row

    float acc[4][4];
#pragma unroll
    for (int nn = 0; nn < 4; nn++)
#pragma unroll
        for (int k = 0; k < 4; k++) acc[nn][k] = 0.f;

#pragma unroll 1
    for (int pp = 0; pp < 2; pp++) {
        const ushort_t* src = pp ? ginl : ginh;
        for (int c = tid; c < 1920; c += 256) {
            int px = c >> 3, j = c & 7;
            int iy = px / 20, ix = px - iy * 20;
            int gy = y0 - 2 + iy, gx = x0 - 2 + ix;
            bool ok = (unsigned)gy < (unsigned)H && (unsigned)gx < (unsigned)W;
            const void* g = src + (ok ? (((size_t)gy * W + gx) * 64 + j * 8)
                                      : (size_t)0);
            cp_async16z(sinb + (uint32_t)(px * 128 + ((j ^ (px & 7)) << 4)),
                        g, ok);
        }
        asm volatile("cp.async.commit_group;");
        {   // stage tap 0 weights into buffer 0
            for (int c = tid; c < 256; c += 256)
                cp_async16(swb + c * 16, gwh + c * 8);
            if (pp == 0)
                for (int c = tid; c < 256; c += 256)
                    cp_async16(swb + 4096 + c * 16, gwl + c * 8);
            asm volatile("cp.async.commit_group;");
        }
        asm volatile("cp.async.wait_group 0;" ::: "memory");
        __syncthreads();

#pragma unroll 1
        for (int tap = 0; tap < 25; tap++) {
            if (tap < 24) {
                uint32_t bufo = (uint32_t)(((tap + 1) & 1) * 8192);
                const ushort_t* wh = gwh + (tap + 1) * 2048;
                for (int c = tid; c < 256; c += 256)
                    cp_async16(swb + bufo + c * 16, wh + c * 8);
                if (pp == 0) {
                    const ushort_t* wl = gwl + (tap + 1) * 2048;
                    for (int c = tid; c < 256; c += 256)
                        cp_async16(swb + bufo + 4096 + c * 16, wl + c * 8);
                }
                asm volatile("cp.async.commit_group;");
            }
            int ky = tap / 5, kx = tap - ky * 5;
            int q = (wid + ky) * 20 + (ax + kx);
            uint32_t qbase = sinb + (uint32_t)(q * 128);
            int q7 = q & 7;
            uint32_t wb0 = swb + (uint32_t)((tap & 1) * 8192) +
                           (uint32_t)(bro * 64);
#pragma unroll
            for (int cc = 0; cc < 4; cc++) {
                uint32_t a[4];
                ldsm_x4(a, qbase + (uint32_t)(((2 * cc + ach) ^ q7) << 4));
                uint32_t bcc = wb0 + (uint32_t)(cc * 1024);  // 16 rows * 64B
#pragma unroll
                for (int nn = 0; nn < 4; nn++) {
                    uint32_t boff = (uint32_t)((nn ^ bsw) << 4);
                    uint32_t bh[2];
                    ldsm_x2t(bh, bcc + boff);
                    mma16816(acc[nn], a, bh);
                    if (pp == 0) {
                        uint32_t bl[2];
                        ldsm_x2t(bl, bcc + 4096 + boff);
                        mma16816(acc[nn], a, bl);
                    }
                }
            }
            if (tap < 24) {
                asm volatile("cp.async.wait_group 0;" ::: "memory");
                __syncthreads();
            }
        }
        __syncthreads();
    }

    // epilogue: bias + relu, planar f32 out
    float* gout = g_t2 + (size_t)(uu * B + b) * 32 * HW;
    int pxa = lane >> 2;
    int coq = (lane & 3) << 1;
    int gy = y0 + wid;
    int gxa = x0 + pxa, gxb = gxa + 8;
#pragma unroll
    for (int nn = 0; nn < 4; nn++) {
        int c0 = nn * 8 + coq;
        float b0 = s_bias[c0], b1v = s_bias[c0 + 1];
        gout[(size_t)c0 * HW + (size_t)gy * W + gxa] =
            fmaxf(acc[nn][0] + b0, 0.f);
        gout[(size_t)(c0 + 1) * HW + (size_t)gy * W + gxa] =
            fmaxf(acc[nn][1] + b1v, 0.f);
        gout[(size_t)c0 * HW + (size_t)gy * W + gxb] =
            fmaxf(acc[nn][2] + b0, 0.f);
        gout[(size_t)(c0 + 1) * HW + (size_t)gy * W + gxb] =
            fmaxf(acc[nn][3] + b1v, 0.f);
    }
}

// ---------------------------------------------------------------------------
// conv3: 5x5, 32->1, bias. (unchanged; reads g_t2 planar f32)
// ---------------------------------------------------------------------------
__global__ __launch_bounds__(256) void conv3_kernel(
    const float* __restrict__ w3, const float* __restrict__ b3,
    float* __restrict__ out, int H, int W, int B, int unitBase,
    int interleave) {
    __shared__ float s_in[16 * 400];
    __shared__ float s_w[16 * 25];

    int tx = threadIdx.x, ty = threadIdx.y;
    int tid = ty * 16 + tx;
    int bz = blockIdx.z;
    int b = bz % B, uu = bz / B;
    int unit = unitBase + uu;

    size_t HW = (size_t)H * W;
    const float* gin = g_t2 + (size_t)(uu * B + b) * 32 * HW;
    const float* gw = w3 + (size_t)unit * 800;
    int bx0 = blockIdx.x * 16 - 2, by0 = blockIdx.y * 16 - 2;

    float acc = 0.f;
    for (int cc = 0; cc < 2; cc++) {
        __syncthreads();
        for (int i = tid; i < 16 * 400; i += 256) {
            int ci = i / 400;
            int r = i - ci * 400;
            int iy = r / 20, ix = r - iy * 20;
            int gy = by0 + iy, gx = bx0 + ix;
            float v = 0.f;
            if ((unsigned)gy < (unsigned)H && (unsigned)gx < (unsigned)W)
                v = gin[(size_t)(cc * 16 + ci) * HW + (size_t)gy * W + gx];
            s_in[i] = v;
        }
        for (int i = tid; i < 400; i += 256) s_w[i] = gw[cc * 400 + i];
        __syncthreads();

#pragma unroll 1
        for (int ci = 0; ci < 16; ci++) {
#pragma unroll
            for (int ky = 0; ky < 5; ky++)
#pragma unroll
                for (int kx = 0; kx < 5; kx++)
                    acc += s_in[ci * 400 + (ty + ky) * 20 + tx + kx] *
                           s_w[ci * 25 + ky * 5 + kx];
        }
    }
    acc += b3[unit];

    int y = blockIdx.y * 16 + ty, x = blockIdx.x * 16 + tx;
    if (interleave) {
        int dy = uu >> 1, dx = uu & 1;
        out[(size_t)b * 4 * HW + (size_t)(2 * y + dy) * (2 * W) +
            (2 * x + dx)] = acc;
    } else {
        out[(size_t)b * HW + (size_t)y * W + x] = acc;
    }
}

// ---------------------------------------------------------------------------
// MSF input: bilinear upscales (half-pixel, edge-clamped) + x16.
// ---------------------------------------------------------------------------
__device__ __forceinline__ float bilin(const float* __restrict__ p, int b,
                                       int H, int W, int oy, int ox, int s) {
    float sy = (oy + 0.5f) / (float)s - 0.5f;
    float sx = (ox + 0.5f) / (float)s - 0.5f;
    int y0 = (int)floorf(sy), x0 = (int)floorf(sx);
    float fy = sy - (float)y0, fx = sx - (float)x0;
    int y0c = min(max(y0, 0), H - 1), y1c = min(max(y0 + 1, 0), H - 1);
    int x0c = min(max(x0, 0), W - 1), x1c = min(max(x0 + 1, 0), W - 1);
    const float* pb = p + (size_t)b * H * W;
    float v00 = pb[(size_t)y0c * W + x0c];
    float v01 = pb[(size_t)y0c * W + x1c];
    float v10 = pb[(size_t)y1c * W + x0c];
    float v11 = pb[(size_t)y1c * W + x1c];
    return (1.f - fy) * ((1.f - fx) * v00 + fx * v01) +
           fy * ((1.f - fx) * v10 + fx * v11);
}

__global__ void msf_in_kernel(const float* __restrict__ x2,
                              const float* __restrict__ x4,
                              const float* __restrict__ x8,
                              const float* __restrict__ x16) {
    int idx = blockIdx.x * blockDim.x + threadIdx.x;
    if (idx >= 2 * 1024 * 1024) return;
    int b = idx >> 20;
    int r = idx & ((1 << 20) - 1);
    int y = r >> 10, x = r & 1023;
    float v = x16[idx];
    v += bilin(x2, b, 128, 128, y, x, 8);
    v += bilin(x4, b, 256, 256, y, x, 4);
    v += bilin(x8, b, 512, 512, y, x, 2);
    g_msf[idx] = v;
}

// ---------------------------------------------------------------------------
// Launch
// ---------------------------------------------------------------------------
extern "C" void kernel_launch(void* const* d_in, const int* in_sizes, int n_in,
                              void* d_out, int out_size) {
    const float* image = (const float*)d_in[0];
    const float* w1 = (const float*)d_in[1];
    const float* b1 = (const float*)d_in[2];
    const float* w2 = (const float*)d_in[3];
    const float* b2 = (const float*)d_in[4];
    const float* w3 = (const float*)d_in[5];
    const float* b3 = (const float*)d_in[6];
    float* out = (float*)d_out;

    float* o_x2 = out;                // 2*128*128
    float* o_x4 = out + 32768;        // 2*256*256
    float* o_x8 = out + 163840;       // 2*512*512
    float* o_x16 = out + 688128;      // 2*1024*1024
    float* o_msf = out + 2785280;     // 2*1024*1024
    const int B = 2;

    prep_weights<<<256, 256>>>(w1, w2);

    const float* sin[4] = {image, o_x2, o_x4, o_x8};
    float* sout[4] = {o_x2, o_x4, o_x8, o_x16};
    int sH[4] = {64, 128, 256, 512};
    for (int s = 0; s < 4; s++) {
        int H = sH[s], W = sH[s];
        int ub = s * 4;
        dim3 grid1(W / 16, H / 16, B * 4);
        dim3 grid2(W / 16, H / 8, B * 4);
        conv1_kernel<<<grid1, 256>>>(sin[s], 0, b1, H, W, B, ub);
        conv2_mma_kernel<<<grid2, 256>>>(b2, H, W, B, ub);
        conv3_kernel<<<grid1, dim3(16, 16)>>>(w3, b3, sout[s], H, W, B, ub, 1);
    }

    msf_in_kernel<<<(2 * 1024 * 1024) / 256, 256>>>(o_x2, o_x4, o_x8, o_x16);
    {
        int H = 1024, W = 1024;
        dim3 grid1(W / 16, H / 16, B * 1);
        dim3 grid2(W / 16, H / 8, B * 1);
        conv1_kernel<<<grid1, 256>>>(nullptr, 1, b1, H, W, B, 16);
        conv2_mma_kernel<<<grid2, 256>>>(b2, H, W, B, 16);
        conv3_kernel<<<grid1, dim3(16, 16)>>>(w3, b3, o_msf, H, W, B, 16, 0);
    }
}